// round 4
// baseline (speedup 1.0000x reference)
#include <cuda_runtime.h>
#include <cstdint>

#define M_ROWS 16384
#define IN_F   2048
#define OUT_F  2048
#define SCAN_BLOCKS 256          // blocks 0..255 also scan 8 weight rows each
#define GRID_BLOCKS (M_ROWS / 8) // 2048

// Exact identity: out[m,n] = rowsum(x[m]) - 2 * sum_{k: w[n,k] < 0} x[m,k]
// (b_weight = sign(sign(w)+0.5) is -1 iff w < 0, else +1 including w == 0).

__device__ unsigned short g_neg_idx[(size_t)OUT_F * IN_F];  // 8 MB scratch
__device__ int            g_neg_cnt[OUT_F];
__device__ unsigned char  g_neg_flag[OUT_F];                // 1 iff cnt > 0
__device__ int            g_done = 0;   // scan-complete counter (reset at exit)
__device__ int            g_exit = 0;   // exit counter for the reset

__global__ void __launch_bounds__(256) fused_kernel(
    const float* __restrict__ x,
    const float* __restrict__ w,
    float*       __restrict__ out)
{
    const int tid  = threadIdx.x;
    const int warp = tid >> 5;
    const int lane = tid & 31;
    const unsigned lt_mask = (1u << lane) - 1u;

    // ---------------- Phase A (blocks < SCAN_BLOCKS): weight scan ----------
    if (blockIdx.x < SCAN_BLOCKS) {
        const int n = blockIdx.x * 8 + warp;
        const float4* wr = reinterpret_cast<const float4*>(w + (size_t)n * IN_F);
        unsigned short* idx = g_neg_idx + (size_t)n * IN_F;
        int cnt = 0;

        #pragma unroll 4
        for (int it = 0; it < 16; it++) {
            const int i4 = it * 32 + lane;
            const float4 v = __ldcs(wr + i4);
            const int kb = i4 * 4;
            unsigned b;
            b = __ballot_sync(0xffffffffu, v.x < 0.0f);
            if (v.x < 0.0f) idx[cnt + __popc(b & lt_mask)] = (unsigned short)(kb + 0);
            cnt += __popc(b);
            b = __ballot_sync(0xffffffffu, v.y < 0.0f);
            if (v.y < 0.0f) idx[cnt + __popc(b & lt_mask)] = (unsigned short)(kb + 1);
            cnt += __popc(b);
            b = __ballot_sync(0xffffffffu, v.z < 0.0f);
            if (v.z < 0.0f) idx[cnt + __popc(b & lt_mask)] = (unsigned short)(kb + 2);
            cnt += __popc(b);
            b = __ballot_sync(0xffffffffu, v.w < 0.0f);
            if (v.w < 0.0f) idx[cnt + __popc(b & lt_mask)] = (unsigned short)(kb + 3);
            cnt += __popc(b);
        }
        if (lane == 0) {
            g_neg_cnt[n]  = cnt;
            g_neg_flag[n] = (cnt > 0) ? 1 : 0;
        }
        __syncthreads();
        if (tid == 0) {
            __threadfence();               // publish idx/cnt/flag before counting
            atomicAdd(&g_done, 1);
        }
    }

    // ---------------- Phase B (all blocks): rowsums for 8 x-rows -----------
    const int m = blockIdx.x * 8 + warp;
    const float* xrow = x + (size_t)m * IN_F;
    const float4* xr4 = reinterpret_cast<const float4*>(xrow);
    float4* orow = reinterpret_cast<float4*>(out + (size_t)m * OUT_F);

    float s0 = 0.0f, s1 = 0.0f;
    #pragma unroll
    for (int it = 0; it < 16; it += 2) {
        const float4 a = __ldcs(xr4 + it * 32 + lane);
        const float4 b = __ldcs(xr4 + (it + 1) * 32 + lane);
        s0 += (a.x + a.y) + (a.z + a.w);
        s1 += (b.x + b.y) + (b.z + b.w);
    }
    float s = s0 + s1;
    #pragma unroll
    for (int o = 16; o > 0; o >>= 1)
        s += __shfl_xor_sync(0xffffffffu, s, o);
    const float S = s;

    // ---------------- Device-side dependency: wait for scan ----------------
    if (tid == 0) {
        while (atomicAdd(&g_done, 0) < SCAN_BLOCKS)
            __nanosleep(64);
        __threadfence();                   // acquire scanner writes
    }
    __syncthreads();

    // ---------------- Phase C: flags + output ------------------------------
    __shared__ unsigned char sflag[OUT_F];
    const unsigned long long fchunk =
        __ldcg(reinterpret_cast<const unsigned long long*>(g_neg_flag) + tid);
    const int any_neg = __syncthreads_or(fchunk != 0ull);

    // Exit/reset protocol: last block to pass the wait resets the counters so
    // every graph replay starts from the same state. All blocks have passed
    // the spin before the reset can fire.
    if (tid == 0) {
        const int p = atomicAdd(&g_exit, 1);
        if (p == GRID_BLOCKS - 1) {
            g_done = 0;
            g_exit = 0;
            __threadfence();
        }
    }

    if (!any_neg) {
        const float4 v = make_float4(S, S, S, S);
        #pragma unroll
        for (int it = 0; it < 16; it++)
            orow[it * 32 + lane] = v;
    } else {
        reinterpret_cast<unsigned long long*>(sflag)[tid] = fchunk;
        __syncthreads();
        #pragma unroll 4
        for (int it = 0; it < 16; it++) {
            const int i4 = it * 32 + lane;
            const int n0 = i4 * 4;
            float4 v = make_float4(S, S, S, S);
            const uchar4 f = *reinterpret_cast<const uchar4*>(sflag + n0);
            if (f.x | f.y | f.z | f.w) {
                if (f.x) {
                    float c = 0.0f;
                    const int cnt = __ldcg(g_neg_cnt + n0 + 0);
                    const unsigned short* id = g_neg_idx + (size_t)(n0 + 0) * IN_F;
                    for (int j = 0; j < cnt; j++) c += __ldg(xrow + __ldcg(id + j));
                    v.x = S - 2.0f * c;
                }
                if (f.y) {
                    float c = 0.0f;
                    const int cnt = __ldcg(g_neg_cnt + n0 + 1);
                    const unsigned short* id = g_neg_idx + (size_t)(n0 + 1) * IN_F;
                    for (int j = 0; j < cnt; j++) c += __ldg(xrow + __ldcg(id + j));
                    v.y = S - 2.0f * c;
                }
                if (f.z) {
                    float c = 0.0f;
                    const int cnt = __ldcg(g_neg_cnt + n0 + 2);
                    const unsigned short* id = g_neg_idx + (size_t)(n0 + 2) * IN_F;
                    for (int j = 0; j < cnt; j++) c += __ldg(xrow + __ldcg(id + j));
                    v.z = S - 2.0f * c;
                }
                if (f.w) {
                    float c = 0.0f;
                    const int cnt = __ldcg(g_neg_cnt + n0 + 3);
                    const unsigned short* id = g_neg_idx + (size_t)(n0 + 3) * IN_F;
                    for (int j = 0; j < cnt; j++) c += __ldg(xrow + __ldcg(id + j));
                    v.w = S - 2.0f * c;
                }
            }
            orow[i4] = v;
        }
    }
}

// ---------------------------------------------------------------------------
// d_in[0] = x [M, IN_F] fp32, d_in[1] = weight [OUT_F, IN_F] fp32.
// d_out = [M, OUT_F] fp32.
// ---------------------------------------------------------------------------
extern "C" void kernel_launch(void* const* d_in, const int* in_sizes, int n_in,
                              void* d_out, int out_size)
{
    const float* x = (const float*)d_in[0];
    const float* w = (const float*)d_in[1];
    float* out = (float*)d_out;

    fused_kernel<<<GRID_BLOCKS, 256>>>(x, w, out);
}

// round 5
// speedup vs baseline: 1.0039x; 1.0039x over previous
#include <cuda_runtime.h>
#include <cstdint>

#define M_ROWS 16384
#define IN_F   2048
#define OUT_F  2048
#define SCAN_BLOCKS 256          // blocks 0..255 also scan 8 weight rows each
#define GRID_BLOCKS (M_ROWS / 8) // 2048

// Exact identity: out[m,n] = rowsum(x[m]) - 2 * sum_{k: w[n,k] < 0} x[m,k]
// (b_weight = sign(sign(w)+0.5) is -1 iff w < 0, else +1 including w == 0).

__device__ unsigned short g_neg_idx[(size_t)OUT_F * IN_F];  // 8 MB scratch
__device__ int            g_neg_cnt[OUT_F];
__device__ unsigned char  g_neg_flag[OUT_F];                // 1 iff cnt > 0
__device__ int            g_done = 0;   // scan-complete counter (reset at exit)
__device__ int            g_exit = 0;   // exit counter for the reset

__global__ void __launch_bounds__(256) fused_kernel(
    const float* __restrict__ x,
    const float* __restrict__ w,
    float*       __restrict__ out)
{
    const int tid  = threadIdx.x;
    const int warp = tid >> 5;
    const int lane = tid & 31;
    const unsigned lt_mask = (1u << lane) - 1u;

    // ---------------- Phase A (blocks < SCAN_BLOCKS): weight scan ----------
    if (blockIdx.x < SCAN_BLOCKS) {
        const int n = blockIdx.x * 8 + warp;
        const float4* wr = reinterpret_cast<const float4*>(w + (size_t)n * IN_F);
        unsigned short* idx = g_neg_idx + (size_t)n * IN_F;
        int cnt = 0;

        #pragma unroll 4
        for (int it = 0; it < 16; it++) {
            const int i4 = it * 32 + lane;
            const float4 v = __ldcs(wr + i4);
            const int kb = i4 * 4;
            unsigned b;
            b = __ballot_sync(0xffffffffu, v.x < 0.0f);
            if (v.x < 0.0f) idx[cnt + __popc(b & lt_mask)] = (unsigned short)(kb + 0);
            cnt += __popc(b);
            b = __ballot_sync(0xffffffffu, v.y < 0.0f);
            if (v.y < 0.0f) idx[cnt + __popc(b & lt_mask)] = (unsigned short)(kb + 1);
            cnt += __popc(b);
            b = __ballot_sync(0xffffffffu, v.z < 0.0f);
            if (v.z < 0.0f) idx[cnt + __popc(b & lt_mask)] = (unsigned short)(kb + 2);
            cnt += __popc(b);
            b = __ballot_sync(0xffffffffu, v.w < 0.0f);
            if (v.w < 0.0f) idx[cnt + __popc(b & lt_mask)] = (unsigned short)(kb + 3);
            cnt += __popc(b);
        }
        if (lane == 0) {
            g_neg_cnt[n]  = cnt;
            g_neg_flag[n] = (cnt > 0) ? 1 : 0;
        }
        __syncthreads();
        if (tid == 0) {
            __threadfence();               // publish idx/cnt/flag before counting
            atomicAdd(&g_done, 1);
        }
    }

    // ---------------- Phase B (all blocks): rowsums for 8 x-rows -----------
    const int m = blockIdx.x * 8 + warp;
    const float* xrow = x + (size_t)m * IN_F;
    const float4* xr4 = reinterpret_cast<const float4*>(xrow);
    float4* orow = reinterpret_cast<float4*>(out + (size_t)m * OUT_F);

    float s0 = 0.0f, s1 = 0.0f;
    #pragma unroll
    for (int it = 0; it < 16; it += 2) {
        const float4 a = __ldcs(xr4 + it * 32 + lane);
        const float4 b = __ldcs(xr4 + (it + 1) * 32 + lane);
        s0 += (a.x + a.y) + (a.z + a.w);
        s1 += (b.x + b.y) + (b.z + b.w);
    }
    float s = s0 + s1;
    #pragma unroll
    for (int o = 16; o > 0; o >>= 1)
        s += __shfl_xor_sync(0xffffffffu, s, o);
    const float S = s;

    // ---------------- Device-side dependency: wait for scan ----------------
    if (tid == 0) {
        while (atomicAdd(&g_done, 0) < SCAN_BLOCKS)
            __nanosleep(64);
        __threadfence();                   // acquire scanner writes
    }
    __syncthreads();

    // ---------------- Phase C: flags + output ------------------------------
    __shared__ unsigned char sflag[OUT_F];
    const unsigned long long fchunk =
        __ldcg(reinterpret_cast<const unsigned long long*>(g_neg_flag) + tid);
    const int any_neg = __syncthreads_or(fchunk != 0ull);

    // Exit/reset protocol: last block to pass the wait resets the counters so
    // every graph replay starts from the same state. All blocks have passed
    // the spin before the reset can fire.
    if (tid == 0) {
        const int p = atomicAdd(&g_exit, 1);
        if (p == GRID_BLOCKS - 1) {
            g_done = 0;
            g_exit = 0;
            __threadfence();
        }
    }

    if (!any_neg) {
        const float4 v = make_float4(S, S, S, S);
        #pragma unroll
        for (int it = 0; it < 16; it++)
            orow[it * 32 + lane] = v;
    } else {
        reinterpret_cast<unsigned long long*>(sflag)[tid] = fchunk;
        __syncthreads();
        #pragma unroll 4
        for (int it = 0; it < 16; it++) {
            const int i4 = it * 32 + lane;
            const int n0 = i4 * 4;
            float4 v = make_float4(S, S, S, S);
            const uchar4 f = *reinterpret_cast<const uchar4*>(sflag + n0);
            if (f.x | f.y | f.z | f.w) {
                if (f.x) {
                    float c = 0.0f;
                    const int cnt = __ldcg(g_neg_cnt + n0 + 0);
                    const unsigned short* id = g_neg_idx + (size_t)(n0 + 0) * IN_F;
                    for (int j = 0; j < cnt; j++) c += __ldg(xrow + __ldcg(id + j));
                    v.x = S - 2.0f * c;
                }
                if (f.y) {
                    float c = 0.0f;
                    const int cnt = __ldcg(g_neg_cnt + n0 + 1);
                    const unsigned short* id = g_neg_idx + (size_t)(n0 + 1) * IN_F;
                    for (int j = 0; j < cnt; j++) c += __ldg(xrow + __ldcg(id + j));
                    v.y = S - 2.0f * c;
                }
                if (f.z) {
                    float c = 0.0f;
                    const int cnt = __ldcg(g_neg_cnt + n0 + 2);
                    const unsigned short* id = g_neg_idx + (size_t)(n0 + 2) * IN_F;
                    for (int j = 0; j < cnt; j++) c += __ldg(xrow + __ldcg(id + j));
                    v.z = S - 2.0f * c;
                }
                if (f.w) {
                    float c = 0.0f;
                    const int cnt = __ldcg(g_neg_cnt + n0 + 3);
                    const unsigned short* id = g_neg_idx + (size_t)(n0 + 3) * IN_F;
                    for (int j = 0; j < cnt; j++) c += __ldg(xrow + __ldcg(id + j));
                    v.w = S - 2.0f * c;
                }
            }
            orow[i4] = v;
        }
    }
}

// ---------------------------------------------------------------------------
// d_in[0] = x [M, IN_F] fp32, d_in[1] = weight [OUT_F, IN_F] fp32.
// d_out = [M, OUT_F] fp32.
// ---------------------------------------------------------------------------
extern "C" void kernel_launch(void* const* d_in, const int* in_sizes, int n_in,
                              void* d_out, int out_size)
{
    const float* x = (const float*)d_in[0];
    const float* w = (const float*)d_in[1];
    float* out = (float*)d_out;

    fused_kernel<<<GRID_BLOCKS, 256>>>(x, w, out);
}

// round 6
// speedup vs baseline: 1.0134x; 1.0095x over previous
#include <cuda_runtime.h>
#include <cstdint>

#define M_ROWS 16384
#define IN_F   2048
#define OUT_F  2048
#define SCAN_BLOCKS 256          // blocks 0..255 also scan 8 weight rows each
#define GRID_BLOCKS (M_ROWS / 8) // 2048

// Exact identity: out[m,n] = rowsum(x[m]) - 2 * sum_{k: w[n,k] < 0} x[m,k]
// (b_weight = sign(sign(w)+0.5) is -1 iff w < 0, else +1 including w == 0).

__device__ unsigned short g_neg_idx[(size_t)OUT_F * IN_F];  // 8 MB scratch
__device__ int            g_neg_cnt[OUT_F];
__device__ unsigned char  g_neg_flag[OUT_F];                // 1 iff cnt > 0
__device__ int            g_done = 0;   // scan-complete counter (reset at exit)
__device__ int            g_exit = 0;   // exit counter for the reset

__global__ void __launch_bounds__(256) fused_kernel(
    const float* __restrict__ x,
    const float* __restrict__ w,
    float*       __restrict__ out)
{
    const int tid  = threadIdx.x;
    const int warp = tid >> 5;
    const int lane = tid & 31;
    const unsigned lt_mask = (1u << lane) - 1u;

    // ---------------- Phase A (blocks < SCAN_BLOCKS): weight scan ----------
    if (blockIdx.x < SCAN_BLOCKS) {
        const int n = blockIdx.x * 8 + warp;
        const float4* wr = reinterpret_cast<const float4*>(w + (size_t)n * IN_F);
        unsigned short* idx = g_neg_idx + (size_t)n * IN_F;
        int cnt = 0;

        #pragma unroll 4
        for (int it = 0; it < 16; it++) {
            const int i4 = it * 32 + lane;
            const float4 v = __ldcs(wr + i4);
            const int kb = i4 * 4;
            unsigned b;
            b = __ballot_sync(0xffffffffu, v.x < 0.0f);
            if (v.x < 0.0f) idx[cnt + __popc(b & lt_mask)] = (unsigned short)(kb + 0);
            cnt += __popc(b);
            b = __ballot_sync(0xffffffffu, v.y < 0.0f);
            if (v.y < 0.0f) idx[cnt + __popc(b & lt_mask)] = (unsigned short)(kb + 1);
            cnt += __popc(b);
            b = __ballot_sync(0xffffffffu, v.z < 0.0f);
            if (v.z < 0.0f) idx[cnt + __popc(b & lt_mask)] = (unsigned short)(kb + 2);
            cnt += __popc(b);
            b = __ballot_sync(0xffffffffu, v.w < 0.0f);
            if (v.w < 0.0f) idx[cnt + __popc(b & lt_mask)] = (unsigned short)(kb + 3);
            cnt += __popc(b);
        }
        if (lane == 0) {
            g_neg_cnt[n]  = cnt;
            g_neg_flag[n] = (cnt > 0) ? 1 : 0;
        }
        __syncthreads();
        if (tid == 0) {
            __threadfence();               // publish idx/cnt/flag before counting
            atomicAdd(&g_done, 1);
        }
    }

    // ---------------- Phase B (all blocks): rowsums for 8 x-rows -----------
    const int m = blockIdx.x * 8 + warp;
    const float* xrow = x + (size_t)m * IN_F;
    const float4* xr4 = reinterpret_cast<const float4*>(xrow);
    float4* orow = reinterpret_cast<float4*>(out + (size_t)m * OUT_F);

    float s0 = 0.0f, s1 = 0.0f;
    #pragma unroll
    for (int it = 0; it < 16; it += 2) {
        const float4 a = __ldcs(xr4 + it * 32 + lane);
        const float4 b = __ldcs(xr4 + (it + 1) * 32 + lane);
        s0 += (a.x + a.y) + (a.z + a.w);
        s1 += (b.x + b.y) + (b.z + b.w);
    }
    float s = s0 + s1;
    #pragma unroll
    for (int o = 16; o > 0; o >>= 1)
        s += __shfl_xor_sync(0xffffffffu, s, o);
    const float S = s;

    // ---------------- Device-side dependency: wait for scan ----------------
    if (tid == 0) {
        while (atomicAdd(&g_done, 0) < SCAN_BLOCKS)
            __nanosleep(64);
        __threadfence();                   // acquire scanner writes
    }
    __syncthreads();

    // ---------------- Phase C: flags + output ------------------------------
    __shared__ unsigned char sflag[OUT_F];
    const unsigned long long fchunk =
        __ldcg(reinterpret_cast<const unsigned long long*>(g_neg_flag) + tid);
    const int any_neg = __syncthreads_or(fchunk != 0ull);

    // Exit/reset protocol: last block to pass the wait resets the counters so
    // every graph replay starts from the same state. All blocks have passed
    // the spin before the reset can fire.
    if (tid == 0) {
        const int p = atomicAdd(&g_exit, 1);
        if (p == GRID_BLOCKS - 1) {
            g_done = 0;
            g_exit = 0;
            __threadfence();
        }
    }

    if (!any_neg) {
        const float4 v = make_float4(S, S, S, S);
        #pragma unroll
        for (int it = 0; it < 16; it++)
            orow[it * 32 + lane] = v;
    } else {
        reinterpret_cast<unsigned long long*>(sflag)[tid] = fchunk;
        __syncthreads();
        #pragma unroll 4
        for (int it = 0; it < 16; it++) {
            const int i4 = it * 32 + lane;
            const int n0 = i4 * 4;
            float4 v = make_float4(S, S, S, S);
            const uchar4 f = *reinterpret_cast<const uchar4*>(sflag + n0);
            if (f.x | f.y | f.z | f.w) {
                if (f.x) {
                    float c = 0.0f;
                    const int cnt = __ldcg(g_neg_cnt + n0 + 0);
                    const unsigned short* id = g_neg_idx + (size_t)(n0 + 0) * IN_F;
                    for (int j = 0; j < cnt; j++) c += __ldg(xrow + __ldcg(id + j));
                    v.x = S - 2.0f * c;
                }
                if (f.y) {
                    float c = 0.0f;
                    const int cnt = __ldcg(g_neg_cnt + n0 + 1);
                    const unsigned short* id = g_neg_idx + (size_t)(n0 + 1) * IN_F;
                    for (int j = 0; j < cnt; j++) c += __ldg(xrow + __ldcg(id + j));
                    v.y = S - 2.0f * c;
                }
                if (f.z) {
                    float c = 0.0f;
                    const int cnt = __ldcg(g_neg_cnt + n0 + 2);
                    const unsigned short* id = g_neg_idx + (size_t)(n0 + 2) * IN_F;
                    for (int j = 0; j < cnt; j++) c += __ldg(xrow + __ldcg(id + j));
                    v.z = S - 2.0f * c;
                }
                if (f.w) {
                    float c = 0.0f;
                    const int cnt = __ldcg(g_neg_cnt + n0 + 3);
                    const unsigned short* id = g_neg_idx + (size_t)(n0 + 3) * IN_F;
                    for (int j = 0; j < cnt; j++) c += __ldg(xrow + __ldcg(id + j));
                    v.w = S - 2.0f * c;
                }
            }
            orow[i4] = v;
        }
    }
}

// ---------------------------------------------------------------------------
// d_in[0] = x [M, IN_F] fp32, d_in[1] = weight [OUT_F, IN_F] fp32.
// d_out = [M, OUT_F] fp32.
// ---------------------------------------------------------------------------
extern "C" void kernel_launch(void* const* d_in, const int* in_sizes, int n_in,
                              void* d_out, int out_size)
{
    const float* x = (const float*)d_in[0];
    const float* w = (const float*)d_in[1];
    float* out = (float*)d_out;

    fused_kernel<<<GRID_BLOCKS, 256>>>(x, w, out);
}

// round 7
// speedup vs baseline: 1.1701x; 1.1546x over previous
#include <cuda_runtime.h>
#include <cstdint>

#define M_ROWS 16384
#define IN_F   2048
#define OUT_F  2048

// Exact identity: out[m,n] = rowsum(x[m]) - 2 * sum_{k: w[n,k] < 0} x[m,k]
// (b_weight = sign(sign(w)+0.5) is -1 iff w < 0, else +1 including w == 0).
//
// Negative-index lists are stored as 8 independent 256-element segments per
// weight row (segment s covers k in [s*256, (s+1)*256)), so each warp of the
// scan kernel compacts its own segment with no cross-warp coordination.

__device__ unsigned short g_neg_idx[(size_t)OUT_F * IN_F];   // 8 MB scratch
__device__ unsigned short g_seg_cnt[(size_t)OUT_F * 8];      // per-segment counts
__device__ unsigned char  g_neg_flag[OUT_F];                 // 1 iff any segment nonempty

// ---------------------------------------------------------------------------
// K1: weight scan. Block per weight row (2048 blocks); warp per 256-elem
// segment. Ballot-compacted per-segment index lists.
// ---------------------------------------------------------------------------
__global__ void __launch_bounds__(256) scan_kernel(const float* __restrict__ w)
{
    const int n    = blockIdx.x;
    const int warp = threadIdx.x >> 5;
    const int lane = threadIdx.x & 31;
    const unsigned lt_mask = (1u << lane) - 1u;

    __shared__ int s_cnt[8];

    const float4* wr = reinterpret_cast<const float4*>(w + (size_t)n * IN_F);
    unsigned short* idx = g_neg_idx + (size_t)n * IN_F + warp * 256;
    int cnt = 0;

    #pragma unroll
    for (int it = 0; it < 2; it++) {
        const int i4 = warp * 64 + it * 32 + lane;   // float4 index within row
        const float4 v = wr[i4];
        const int kb = i4 * 4;
        unsigned b;
        b = __ballot_sync(0xffffffffu, v.x < 0.0f);
        if (v.x < 0.0f) idx[cnt + __popc(b & lt_mask)] = (unsigned short)(kb + 0);
        cnt += __popc(b);
        b = __ballot_sync(0xffffffffu, v.y < 0.0f);
        if (v.y < 0.0f) idx[cnt + __popc(b & lt_mask)] = (unsigned short)(kb + 1);
        cnt += __popc(b);
        b = __ballot_sync(0xffffffffu, v.z < 0.0f);
        if (v.z < 0.0f) idx[cnt + __popc(b & lt_mask)] = (unsigned short)(kb + 2);
        cnt += __popc(b);
        b = __ballot_sync(0xffffffffu, v.w < 0.0f);
        if (v.w < 0.0f) idx[cnt + __popc(b & lt_mask)] = (unsigned short)(kb + 3);
        cnt += __popc(b);
    }
    if (lane == 0) s_cnt[warp] = cnt;
    __syncthreads();

    if (threadIdx.x < 8)
        g_seg_cnt[(size_t)n * 8 + threadIdx.x] = (unsigned short)s_cnt[threadIdx.x];
    if (threadIdx.x == 0) {
        int any = 0;
        #pragma unroll
        for (int i = 0; i < 8; i++) any |= s_cnt[i];
        g_neg_flag[n] = (any > 0) ? 1 : 0;
    }
}

// ---------------------------------------------------------------------------
// K2: fused read-reduce-write. Warp per x row (8 rows/block, 2048 blocks).
// Proven R3 structure: no smem x staging, one syncthreads_or path dispatch.
// ---------------------------------------------------------------------------
__global__ void __launch_bounds__(256) out_kernel(
    const float* __restrict__ x,
    float*       __restrict__ out)
{
    __shared__ unsigned char sflag[OUT_F];

    const unsigned long long fchunk =
        reinterpret_cast<const unsigned long long*>(g_neg_flag)[threadIdx.x];
    const int any_neg = __syncthreads_or(fchunk != 0ull);
    if (any_neg) {
        reinterpret_cast<unsigned long long*>(sflag)[threadIdx.x] = fchunk;
        __syncthreads();
    }

    const int warp = threadIdx.x >> 5;
    const int lane = threadIdx.x & 31;
    const int m = blockIdx.x * 8 + warp;

    const float* xrow = x + (size_t)m * IN_F;
    const float4* xr4 = reinterpret_cast<const float4*>(xrow);
    float4* orow = reinterpret_cast<float4*>(out + (size_t)m * OUT_F);

    float s0 = 0.0f, s1 = 0.0f;
    #pragma unroll
    for (int it = 0; it < 16; it += 2) {
        const float4 a = xr4[it * 32 + lane];
        const float4 b = xr4[(it + 1) * 32 + lane];
        s0 += (a.x + a.y) + (a.z + a.w);
        s1 += (b.x + b.y) + (b.z + b.w);
    }
    float s = s0 + s1;
    #pragma unroll
    for (int o = 16; o > 0; o >>= 1)
        s += __shfl_xor_sync(0xffffffffu, s, o);
    const float S = s;

    if (!any_neg) {
        // Pure splat: 16 coalesced STG.128 per lane.
        const float4 v = make_float4(S, S, S, S);
        #pragma unroll
        for (int it = 0; it < 16; it++)
            orow[it * 32 + lane] = v;
    } else {
        // General path: per-column correction over 8 index segments.
        for (int it = 0; it < 16; it++) {
            const int i4 = it * 32 + lane;
            const int n0 = i4 * 4;
            float4 v = make_float4(S, S, S, S);
            const uchar4 f = *reinterpret_cast<const uchar4*>(sflag + n0);
            if (f.x | f.y | f.z | f.w) {
                float* vc = reinterpret_cast<float*>(&v);
                const unsigned char* fc = reinterpret_cast<const unsigned char*>(&f);
                #pragma unroll
                for (int e = 0; e < 4; e++) {
                    if (fc[e]) {
                        const int n = n0 + e;
                        float c = 0.0f;
                        const unsigned short* base = g_neg_idx + (size_t)n * IN_F;
                        const unsigned short* scnt = g_seg_cnt + (size_t)n * 8;
                        #pragma unroll
                        for (int sgi = 0; sgi < 8; sgi++) {
                            const int cnt = scnt[sgi];
                            const unsigned short* id = base + sgi * 256;
                            for (int j = 0; j < cnt; j++) c += __ldg(xrow + id[j]);
                        }
                        vc[e] = S - 2.0f * c;
                    }
                }
            }
            orow[i4] = v;
        }
    }
}

// ---------------------------------------------------------------------------
// d_in[0] = x [M, IN_F] fp32, d_in[1] = weight [OUT_F, IN_F] fp32.
// d_out = [M, OUT_F] fp32.
// ---------------------------------------------------------------------------
extern "C" void kernel_launch(void* const* d_in, const int* in_sizes, int n_in,
                              void* d_out, int out_size)
{
    const float* x = (const float*)d_in[0];
    const float* w = (const float*)d_in[1];
    float* out = (float*)d_out;

    scan_kernel<<<OUT_F, 256>>>(w);
    out_kernel<<<M_ROWS / 8, 256>>>(x, out);
}